// round 5
// baseline (speedup 1.0000x reference)
#include <cuda_runtime.h>
#include <cuda_bf16.h>
#include <math.h>
#include <stdint.h>

#define BSZ 4096
#define NE  6
#define DF  1830
#define DPD 2086
#define DH  512

// Kpad: multiples of 32
#define KP_I1 1056
#define KP_G1 1856
#define KP_E1 2112

// ---------------- scratch (device globals; no allocs allowed) ----------------
__device__ float g_h0 [BSZ*DPD];
__device__ float g_ih1[BSZ*256];
__device__ float g_ih2[BSZ*256];
__device__ float g_gh1[BSZ*512];
__device__ float g_gh2[BSZ*256];
__device__ float g_om [BSZ*NE];
__device__ float g_e1 [BSZ*DH];
__device__ float g_e2 [BSZ*DH];
__device__ float g_e3 [BSZ*DH];
__device__ float g_hd [BSZ*DF];

__device__ __nv_bfloat16 s_iw1h[256*KP_I1],  s_iw1m[256*KP_I1];
__device__ __nv_bfloat16 s_iw2h[256*256],    s_iw2m[256*256];
__device__ __nv_bfloat16 s_iw3h[256*256],    s_iw3m[256*256];
__device__ __nv_bfloat16 s_gw1h[512*KP_G1],  s_gw1m[512*KP_G1];
__device__ __nv_bfloat16 s_gw2h[256*512],    s_gw2m[256*512];
__device__ __nv_bfloat16 s_ew1h[(size_t)NE*512*KP_E1], s_ew1m[(size_t)NE*512*KP_E1];
__device__ __nv_bfloat16 s_ew2h[(size_t)NE*512*512],   s_ew2m[(size_t)NE*512*512];
__device__ __nv_bfloat16 s_ew3h[(size_t)NE*512*512],   s_ew3m[(size_t)NE*512*512];
__device__ __nv_bfloat16 s_hwh[(size_t)DF*512],        s_hwm[(size_t)DF*512];
__device__ float g_hbias[DF];

__device__ __forceinline__ float elu1(float x) { return x > 0.f ? x : expm1f(x); }

__device__ __forceinline__ uint32_t smem_u32(const void* p) {
    uint32_t a;
    asm("{ .reg .u64 t; cvta.to.shared.u64 t, %1; cvt.u32.u64 %0, t; }" : "=r"(a) : "l"(p));
    return a;
}
__device__ __forceinline__ uint32_t pack_split(float x0, float x1, uint32_t& mid) {
    __nv_bfloat16 h0 = __float2bfloat16(x0);
    __nv_bfloat16 h1 = __float2bfloat16(x1);
    float r0 = x0 - __bfloat162float(h0);
    float r1 = x1 - __bfloat162float(h1);
    __nv_bfloat16 m0 = __float2bfloat16(r0);
    __nv_bfloat16 m1 = __float2bfloat16(r1);
    mid = ((uint32_t)__bfloat16_as_ushort(m1) << 16) | __bfloat16_as_ushort(m0);
    return ((uint32_t)__bfloat16_as_ushort(h1) << 16) | __bfloat16_as_ushort(h0);
}
__device__ __forceinline__ void ldm4(uint32_t& r0, uint32_t& r1, uint32_t& r2, uint32_t& r3,
                                     uint32_t addr) {
    asm volatile("ldmatrix.sync.aligned.m8n8.x4.shared.b16 {%0,%1,%2,%3}, [%4];"
                 : "=r"(r0), "=r"(r1), "=r"(r2), "=r"(r3) : "r"(addr));
}
__device__ __forceinline__ void mma16816(float* d, const uint32_t* a, uint32_t b0, uint32_t b1) {
    asm volatile("mma.sync.aligned.m16n8k16.row.col.f32.bf16.bf16.f32 "
                 "{%0,%1,%2,%3}, {%4,%5,%6,%7}, {%8,%9}, {%0,%1,%2,%3};"
                 : "+f"(d[0]), "+f"(d[1]), "+f"(d[2]), "+f"(d[3])
                 : "r"(a[0]), "r"(a[1]), "r"(a[2]), "r"(a[3]), "r"(b0), "r"(b1));
}

// ---------------- smem layout ----------------
constexpr int OFF_OM  = 0;          // NE*128*4 = 3072
constexpr int OFF_AH  = 3072;       // 128 x 80B
constexpr int OFF_AM  = 13312;
constexpr int OFF_B   = 23552;      // 3 stages x (BH 10240 | BM 10240)
constexpr int STAGE   = 20480;
constexpr int SMEM_BYTES = OFF_B + 3 * STAGE;   // 84992

// ---------------------------------------------------------------------------
// bf16x3 split GEMM on mma.sync, pipelined:
//   C[4096, Nw] = act( sum_e omega[:,e] * (A @ W_e) + bias )
// A split once per k-chunk; omega applied on half-width register accumulators
// (tmp covers 32 of the 64 warp N-columns at a time to cap register pressure).
// ---------------------------------------------------------------------------
__global__ void __launch_bounds__(256, 1) gemm_mma(
    const float* __restrict__ A, int lda,
    const float* __restrict__ A2, int K1,
    const __nv_bfloat16* __restrict__ Wh, const __nv_bfloat16* __restrict__ Wm,
    const float* __restrict__ omega,
    const float* __restrict__ bias,
    float* __restrict__ C, int ldc,
    int Nw, int K, int Kpad, int E, int blend, int doElu)
{
    extern __shared__ char smem[];
    const uint32_t sb = smem_u32(smem);
    float* omS = (float*)(smem + OFF_OM);

    const int tid  = threadIdx.x;
    const int lane = tid & 31, warp = tid >> 5;
    const int m_base = (warp & 3) * 32;
    const int n_base = (warp >> 2) * 64;
    const int rowBase = blockIdx.y * 128;
    const int colBase = blockIdx.x * 128;

    for (int i = tid; i < E * 128; i += 256) {
        int e = i >> 7, r = i & 127;
        omS[e * 128 + r] = omega ? omega[(size_t)(rowBase + r) * E + e] : 1.0f;
    }

    float acc[2][8][4];
#pragma unroll
    for (int a = 0; a < 2; a++)
#pragma unroll
        for (int b = 0; b < 8; b++)
#pragma unroll
            for (int c = 0; c < 4; c++) acc[a][b][c] = 0.f;

    const int r  = tid >> 1, h = tid & 1;        // A staging: row, k-half
    const int row = rowBase + r;
    const int lm = lane & 15, lc = lane >> 4;    // ldmatrix A mapping
    const int g  = lane >> 3;
    const int b_row  = ((g >> 1) << 3) + (lane & 7);
    const int b_koff = (g & 1) << 4;

    const int nChunks = Kpad >> 5;
    const int NC = nChunks * E;

    // B stage issue: chunk c -> buffer c%3
    auto issue_stage = [&](int c) {
        const int e  = c % E;
        const int k0 = (c / E) << 5;
        const uint32_t base = sb + OFF_B + (c % 3) * STAGE;
#pragma unroll
        for (int q = 0; q < 4; q++) {
            int cl = tid + q * 256;              // 0..1023
            int bufsel = cl >> 9;
            int rem = cl & 511;
            int n = rem >> 2, j = rem & 3;
            int gn = colBase + n;
            const __nv_bfloat16* W = bufsel ? Wm : Wh;
            const char* src = (const char*)(W + ((size_t)e * Nw + (gn < Nw ? gn : 0)) * Kpad + k0) + j * 16;
            uint32_t dst = base + bufsel * 10240 + n * 80 + j * 16;
            int sz = (gn < Nw) ? 16 : 0;
            asm volatile("cp.async.cg.shared.global [%0], [%1], 16, %2;"
                         :: "r"(dst), "l"(src), "r"(sz));
        }
    };

    issue_stage(0);
    asm volatile("cp.async.commit_group;");
    issue_stage(1);
    asm volatile("cp.async.commit_group;");

    uint32_t aH[2][2][4], aM[2][2][4];           // [kh][m2][4]

    for (int c = 0; c < NC; c++) {
        const int e = c % E;
        if (c < NC - 1) asm volatile("cp.async.wait_group 1;");
        else            asm volatile("cp.async.wait_group 0;");
        __syncthreads();

        if (e == 0) {
            // ---- A split for this k-chunk (no omega) ----
            const int k0 = (c / E) << 5;
            float v[16];
#pragma unroll
            for (int j = 0; j < 16; j++) {
                int k = k0 + h * 16 + j;
                float x = 0.f;
                if (k < K) x = (A2 && k >= K1) ? A2[row * 3 + (k - K1)]
                                               : A[(size_t)row * lda + k];
                v[j] = x;
            }
            uint32_t hi[8], mi[8];
#pragma unroll
            for (int u = 0; u < 8; u++) hi[u] = pack_split(v[2*u], v[2*u+1], mi[u]);
            char* dH = smem + OFF_AH + r * 80 + h * 32;
            char* dM = smem + OFF_AM + r * 80 + h * 32;
            *(uint4*)dH        = make_uint4(hi[0], hi[1], hi[2], hi[3]);
            *(uint4*)(dH + 16) = make_uint4(hi[4], hi[5], hi[6], hi[7]);
            *(uint4*)dM        = make_uint4(mi[0], mi[1], mi[2], mi[3]);
            *(uint4*)(dM + 16) = make_uint4(mi[4], mi[5], mi[6], mi[7]);
            __syncthreads();
            // ---- hoist A fragments into registers (reused across experts) ----
#pragma unroll
            for (int kh = 0; kh < 2; kh++)
#pragma unroll
                for (int m2 = 0; m2 < 2; m2++) {
                    uint32_t ad = (m_base + m2 * 16 + lm) * 80 + kh * 32 + lc * 16;
                    ldm4(aH[kh][m2][0], aH[kh][m2][1], aH[kh][m2][2], aH[kh][m2][3], sb + OFF_AH + ad);
                    ldm4(aM[kh][m2][0], aM[kh][m2][1], aM[kh][m2][2], aM[kh][m2][3], sb + OFF_AM + ad);
                }
        }

        const uint32_t bhB = sb + OFF_B + (c % 3) * STAGE;
        const uint32_t bmB = bhB + 10240;
        const float wA0 = omS[e * 128 + m_base + (lane >> 2)];
        const float wB0 = omS[e * 128 + m_base + (lane >> 2) + 8];
        const float wA1 = omS[e * 128 + m_base + 16 + (lane >> 2)];
        const float wB1 = omS[e * 128 + m_base + 16 + (lane >> 2) + 8];

        // ---- two N-halves: tmp covers 32 cols to cap register pressure ----
#pragma unroll
        for (int half = 0; half < 2; half++) {
            float tmp[2][4][4];
#pragma unroll
            for (int a = 0; a < 2; a++)
#pragma unroll
                for (int b = 0; b < 4; b++)
#pragma unroll
                    for (int cc = 0; cc < 4; cc++) tmp[a][b][cc] = 0.f;
#pragma unroll
            for (int kh = 0; kh < 2; kh++) {
                uint32_t bh[2][4], bm[2][4];
#pragma unroll
                for (int ni = 0; ni < 2; ni++) {
                    uint32_t bd = (n_base + (half * 2 + ni) * 16 + b_row) * 80 + kh * 32 + b_koff;
                    ldm4(bh[ni][0], bh[ni][1], bh[ni][2], bh[ni][3], bhB + bd);
                    ldm4(bm[ni][0], bm[ni][1], bm[ni][2], bm[ni][3], bmB + bd);
                }
#pragma unroll
                for (int ni = 0; ni < 2; ni++)
#pragma unroll
                    for (int m2 = 0; m2 < 2; m2++) {
                        mma16816(tmp[m2][2*ni],   aH[kh][m2], bh[ni][0], bh[ni][1]);  // hi*hi
                        mma16816(tmp[m2][2*ni+1], aH[kh][m2], bh[ni][2], bh[ni][3]);
                        mma16816(tmp[m2][2*ni],   aH[kh][m2], bm[ni][0], bm[ni][1]);  // hi*mid
                        mma16816(tmp[m2][2*ni+1], aH[kh][m2], bm[ni][2], bm[ni][3]);
                        mma16816(tmp[m2][2*ni],   aM[kh][m2], bh[ni][0], bh[ni][1]);  // mid*hi
                        mma16816(tmp[m2][2*ni+1], aM[kh][m2], bh[ni][2], bh[ni][3]);
                    }
            }
#pragma unroll
            for (int m2 = 0; m2 < 2; m2++) {
                float wA = m2 ? wA1 : wA0;
                float wB = m2 ? wB1 : wB0;
#pragma unroll
                for (int nj = 0; nj < 4; nj++) {
                    acc[m2][half * 4 + nj][0] += wA * tmp[m2][nj][0];
                    acc[m2][half * 4 + nj][1] += wA * tmp[m2][nj][1];
                    acc[m2][half * 4 + nj][2] += wB * tmp[m2][nj][2];
                    acc[m2][half * 4 + nj][3] += wB * tmp[m2][nj][3];
                }
            }
        }

        if (c + 2 < NC) issue_stage(c + 2);
        asm volatile("cp.async.commit_group;");
    }

    // ---- epilogue ----
#pragma unroll
    for (int m2 = 0; m2 < 2; m2++) {
        int rlA = m_base + m2 * 16 + (lane >> 2);
        int rlB = rlA + 8;
#pragma unroll
        for (int nj = 0; nj < 8; nj++) {
            int n = colBase + n_base + nj * 8 + ((lane & 3) << 1);
            if (n >= Nw) continue;
            float bA0, bA1, bB0, bB1;
            if (blend) {
                bA0 = bA1 = bB0 = bB1 = 0.f;
                for (int e = 0; e < NE; e++) {
                    float be0 = bias[e * Nw + n], be1 = bias[e * Nw + n + 1];
                    bA0 += omS[e * 128 + rlA] * be0;  bA1 += omS[e * 128 + rlA] * be1;
                    bB0 += omS[e * 128 + rlB] * be0;  bB1 += omS[e * 128 + rlB] * be1;
                }
            } else {
                bA0 = bB0 = bias[n];
                bA1 = bB1 = bias[n + 1];
            }
            float v0 = acc[m2][nj][0] + bA0, v1 = acc[m2][nj][1] + bA1;
            float v2 = acc[m2][nj][2] + bB0, v3 = acc[m2][nj][3] + bB1;
            if (doElu) { v0 = elu1(v0); v1 = elu1(v1); v2 = elu1(v2); v3 = elu1(v3); }
            *(float2*)&C[(size_t)(rowBase + rlA) * ldc + n] = make_float2(v0, v1);
            *(float2*)&C[(size_t)(rowBase + rlB) * ldc + n] = make_float2(v2, v3);
        }
    }
}

// ---------------------------------------------------------------------------
// Weight prep: transpose [K,N] fp32 -> [N,Kpad] bf16 hi/mid (zero pad)
// ---------------------------------------------------------------------------
__global__ void prep_split(const float* __restrict__ W, __nv_bfloat16* __restrict__ oh,
                           __nv_bfloat16* __restrict__ om_, int K, int Nw, int Kpad) {
    __shared__ float t[32][33];
    int e = blockIdx.z;
    const float* Ws = W + (size_t)e * K * Nw;
    __nv_bfloat16* po = oh  + (size_t)e * Nw * Kpad;
    __nv_bfloat16* pm = om_ + (size_t)e * Nw * Kpad;
    int k0 = blockIdx.x * 32, n0 = blockIdx.y * 32;
    int tx = threadIdx.x, ty = threadIdx.y;
#pragma unroll
    for (int i = 0; i < 4; i++) {
        int kk = k0 + ty + i * 8, nn = n0 + tx;
        t[ty + i * 8][tx] = (kk < K && nn < Nw) ? Ws[(size_t)kk * Nw + nn] : 0.f;
    }
    __syncthreads();
#pragma unroll
    for (int i = 0; i < 4; i++) {
        int nn = n0 + ty + i * 8, kk = k0 + tx;
        if (nn < Nw) {
            float x = t[tx][ty + i * 8];
            __nv_bfloat16 hh = __float2bfloat16(x);
            __nv_bfloat16 mm = __float2bfloat16(x - __bfloat162float(hh));
            po[(size_t)nn * Kpad + kk] = hh;
            pm[(size_t)nn * Kpad + kk] = mm;
        }
    }
}

__device__ __forceinline__ float head_w(const float* pw, const float* tw,
                                        const float* dw, const float* vw, int k, int n) {
    if (n < 330) return pw[k * 330 + n];
    if (n < 333) return tw[k * 3 + (n - 330)];
    if (n < 630) return dw[k * 297 + (n - 333)];
    return vw[(size_t)k * 1200 + (n - 630)];
}
__global__ void prep_heads(const float* pw, const float* tw, const float* dw, const float* vw,
                           __nv_bfloat16* oh, __nv_bfloat16* om_) {
    __shared__ float t[32][33];
    int k0 = blockIdx.x * 32, n0 = blockIdx.y * 32;
    int tx = threadIdx.x, ty = threadIdx.y;
#pragma unroll
    for (int i = 0; i < 4; i++) {
        int kk = k0 + ty + i * 8, nn = n0 + tx;
        t[ty + i * 8][tx] = (kk < 512 && nn < DF) ? head_w(pw, tw, dw, vw, kk, nn) : 0.f;
    }
    __syncthreads();
#pragma unroll
    for (int i = 0; i < 4; i++) {
        int nn = n0 + ty + i * 8, kk = k0 + tx;
        if (nn < DF) {
            float x = t[tx][ty + i * 8];
            __nv_bfloat16 hh = __float2bfloat16(x);
            __nv_bfloat16 mm = __float2bfloat16(x - __bfloat162float(hh));
            oh[(size_t)nn * 512 + kk] = hh;
            om_[(size_t)nn * 512 + kk] = mm;
        }
    }
}
__global__ void prep_hbias(const float* pb, const float* tb, const float* db, const float* vb,
                           float* out) {
    int n = blockIdx.x * 256 + threadIdx.x;
    if (n >= DF) return;
    float v;
    if (n < 330) v = pb[n];
    else if (n < 333) v = tb[n - 330];
    else if (n < 630) v = db[n - 333];
    else v = vb[n - 630];
    out[n] = v;
}

// ---------------------------------------------------------------------------
__global__ void assemble_frame(const float* __restrict__ rot, const float* __restrict__ tr,
                               const float* __restrict__ verts, const float* __restrict__ dists) {
    int idx = blockIdx.x * 256 + threadIdx.x;
    if (idx >= BSZ * DF) return;
    int b = idx / DF, c = idx % DF;
    float v;
    if (c < 330) {
        int j = c / 6, s = c % 6;
        v = rot[b * 495 + j * 9 + (s >> 1) * 3 + (s & 1)];
    } else if (c < 333) v = tr[b * 3 + (c - 330)];
    else if (c < 1533)  v = verts[b * 1200 + (c - 333)];
    else                v = dists[b * 297 + (c - 1533)];
    g_h0[(size_t)b * DPD + c] = v;
}

__global__ void gate3_softmax(const float* __restrict__ H, const float* __restrict__ W,
                              const float* __restrict__ b, float* __restrict__ om) {
    int warp = (blockIdx.x * blockDim.x + threadIdx.x) >> 5;
    int lane = threadIdx.x & 31;
    if (warp >= BSZ) return;
    float p[NE] = {};
    for (int k = lane; k < 256; k += 32) {
        float x = H[(size_t)warp * 256 + k];
#pragma unroll
        for (int e = 0; e < NE; e++) p[e] += x * W[k * NE + e];
    }
#pragma unroll
    for (int e = 0; e < NE; e++)
        for (int o = 16; o > 0; o >>= 1) p[e] += __shfl_down_sync(0xffffffffu, p[e], o);
    if (lane == 0) {
        float m = -1e30f;
#pragma unroll
        for (int e = 0; e < NE; e++) { p[e] += b[e]; m = fmaxf(m, p[e]); }
        float s = 0.f;
#pragma unroll
        for (int e = 0; e < NE; e++) { p[e] = expf(p[e] - m); s += p[e]; }
        float inv = 1.f / s;
#pragma unroll
        for (int e = 0; e < NE; e++) om[(size_t)warp * NE + e] = p[e] * inv;
    }
}

__global__ void post_pose(const float* __restrict__ hd, float* __restrict__ out) {
    int idx = blockIdx.x * 256 + threadIdx.x;
    if (idx >= BSZ * 55) return;
    int b = idx / 55, j = idx % 55;
    const float* p = hd + (size_t)b * DF + j * 6;
    float a1x = p[0], a2x = p[1], a1y = p[2], a2y = p[3], a1z = p[4], a2z = p[5];
    float inv = rsqrtf(a1x * a1x + a1y * a1y + a1z * a1z);
    float b1x = a1x * inv, b1y = a1y * inv, b1z = a1z * inv;
    float d = b1x * a2x + b1y * a2y + b1z * a2z;
    float cx = a2x - d * b1x, cy = a2y - d * b1y, cz = a2z - d * b1z;
    float inv2 = rsqrtf(cx * cx + cy * cy + cz * cz);
    float b2x = cx * inv2, b2y = cy * inv2, b2z = cz * inv2;
    float b3x = b1y * b2z - b1z * b2y;
    float b3y = b1z * b2x - b1x * b2z;
    float b3z = b1x * b2y - b1y * b2x;
    float* o = out + (size_t)b * 495 + j * 9;
    o[0] = b1x; o[1] = b2x; o[2] = b3x;
    o[3] = b1y; o[4] = b2y; o[5] = b3y;
    o[6] = b1z; o[7] = b2z; o[8] = b3z;
}

__global__ void post_copy(const float* __restrict__ hd, float* __restrict__ out) {
    const size_t base_t = (size_t)BSZ * 495;
    const size_t base_d = base_t + (size_t)BSZ * 3;
    const size_t base_v = base_d + (size_t)BSZ * 297;
    int idx = blockIdx.x * 256 + threadIdx.x;
    if (idx >= BSZ * 1500) return;
    int b = idx / 1500, c = idx % 1500;
    const float* row = hd + (size_t)b * DF;
    if (c < 3)        out[base_t + (size_t)b * 3 + c]            = row[330 + c];
    else if (c < 300) out[base_d + (size_t)b * 297 + (c - 3)]    = row[333 + (c - 3)];
    else              out[base_v + (size_t)b * 1200 + (c - 300)] = row[630 + (c - 300)];
}

// ---------------------------------------------------------------------------
extern "C" void kernel_launch(void* const* d_in, const int* in_sizes, int n_in,
                              void* d_out, int out_size) {
    const float* rot   = (const float*)d_in[0];
    const float* tr    = (const float*)d_in[1];
    const float* verts = (const float*)d_in[2];
    const float* dists = (const float*)d_in[3];
    const float* bps   = (const float*)d_in[4];
    const float* ogt   = (const float*)d_in[5];
    const float* iw1 = (const float*)d_in[6];  const float* ib1 = (const float*)d_in[7];
    const float* iw2 = (const float*)d_in[8];  const float* ib2 = (const float*)d_in[9];
    const float* iw3 = (const float*)d_in[10]; const float* ib3 = (const float*)d_in[11];
    const float* gw1 = (const float*)d_in[12]; const float* gb1 = (const float*)d_in[13];
    const float* gw2 = (const float*)d_in[14]; const float* gb2 = (const float*)d_in[15];
    const float* gw3 = (const float*)d_in[16]; const float* gb3 = (const float*)d_in[17];
    const float* ew1 = (const float*)d_in[18]; const float* eb1 = (const float*)d_in[19];
    const float* ew2 = (const float*)d_in[20]; const float* eb2 = (const float*)d_in[21];
    const float* ew3 = (const float*)d_in[22]; const float* eb3 = (const float*)d_in[23];
    const float* pw  = (const float*)d_in[24]; const float* pb  = (const float*)d_in[25];
    const float* tw  = (const float*)d_in[26]; const float* tb  = (const float*)d_in[27];
    const float* vw  = (const float*)d_in[28]; const float* vb  = (const float*)d_in[29];
    const float* dw  = (const float*)d_in[30]; const float* db  = (const float*)d_in[31];
    float* out = (float*)d_out;

    cudaFuncSetAttribute(gemm_mma, cudaFuncAttributeMaxDynamicSharedMemorySize, SMEM_BYTES);

    float *h0, *ih1, *ih2, *gh1, *gh2, *om, *e1, *e2, *e3, *hd, *hbias;
    cudaGetSymbolAddress((void**)&h0,  g_h0);
    cudaGetSymbolAddress((void**)&ih1, g_ih1);
    cudaGetSymbolAddress((void**)&ih2, g_ih2);
    cudaGetSymbolAddress((void**)&gh1, g_gh1);
    cudaGetSymbolAddress((void**)&gh2, g_gh2);
    cudaGetSymbolAddress((void**)&om,  g_om);
    cudaGetSymbolAddress((void**)&e1,  g_e1);
    cudaGetSymbolAddress((void**)&e2,  g_e2);
    cudaGetSymbolAddress((void**)&e3,  g_e3);
    cudaGetSymbolAddress((void**)&hd,  g_hd);
    cudaGetSymbolAddress((void**)&hbias, g_hbias);
    __nv_bfloat16 *iw1h,*iw1m,*iw2h,*iw2m,*iw3h,*iw3m,*gw1h,*gw1m,*gw2h,*gw2m;
    __nv_bfloat16 *ew1h,*ew1m,*ew2h,*ew2m,*ew3h,*ew3m,*hwh,*hwm;
    cudaGetSymbolAddress((void**)&iw1h, s_iw1h); cudaGetSymbolAddress((void**)&iw1m, s_iw1m);
    cudaGetSymbolAddress((void**)&iw2h, s_iw2h); cudaGetSymbolAddress((void**)&iw2m, s_iw2m);
    cudaGetSymbolAddress((void**)&iw3h, s_iw3h); cudaGetSymbolAddress((void**)&iw3m, s_iw3m);
    cudaGetSymbolAddress((void**)&gw1h, s_gw1h); cudaGetSymbolAddress((void**)&gw1m, s_gw1m);
    cudaGetSymbolAddress((void**)&gw2h, s_gw2h); cudaGetSymbolAddress((void**)&gw2m, s_gw2m);
    cudaGetSymbolAddress((void**)&ew1h, s_ew1h); cudaGetSymbolAddress((void**)&ew1m, s_ew1m);
    cudaGetSymbolAddress((void**)&ew2h, s_ew2h); cudaGetSymbolAddress((void**)&ew2m, s_ew2m);
    cudaGetSymbolAddress((void**)&ew3h, s_ew3h); cudaGetSymbolAddress((void**)&ew3m, s_ew3m);
    cudaGetSymbolAddress((void**)&hwh,  s_hwh);  cudaGetSymbolAddress((void**)&hwm,  s_hwm);

    dim3 tb32(32, 8);
    prep_split<<<dim3(KP_I1/32, 8, 1),  tb32>>>(iw1, iw1h, iw1m, 1027, 256, KP_I1);
    prep_split<<<dim3(8, 8, 1),         tb32>>>(iw2, iw2h, iw2m, 256, 256, 256);
    prep_split<<<dim3(8, 8, 1),         tb32>>>(iw3, iw3h, iw3m, 256, 256, 256);
    prep_split<<<dim3(KP_G1/32, 16, 1), tb32>>>(gw1, gw1h, gw1m, 1830, 512, KP_G1);
    prep_split<<<dim3(16, 8, 1),        tb32>>>(gw2, gw2h, gw2m, 512, 256, 512);
    prep_split<<<dim3(KP_E1/32, 16, NE),tb32>>>(ew1, ew1h, ew1m, 2086, 512, KP_E1);
    prep_split<<<dim3(16, 16, NE),      tb32>>>(ew2, ew2h, ew2m, 512, 512, 512);
    prep_split<<<dim3(16, 16, NE),      tb32>>>(ew3, ew3h, ew3m, 512, 512, 512);
    prep_heads<<<dim3(16, 58, 1),       tb32>>>(pw, tw, dw, vw, hwh, hwm);
    prep_hbias<<<8, 256>>>(pb, tb, db, vb, hbias);

    assemble_frame<<<(BSZ * DF + 255) / 256, 256>>>(rot, tr, verts, dists);

    const int GY = BSZ / 128;  // 32
    gemm_mma<<<dim3(2, GY), 256, SMEM_BYTES>>>(bps, 1024, ogt, 1024, iw1h, iw1m, nullptr, ib1,
                                               ih1, 256, 256, 1027, KP_I1, 1, 0, 1);
    gemm_mma<<<dim3(2, GY), 256, SMEM_BYTES>>>(ih1, 256, nullptr, 0, iw2h, iw2m, nullptr, ib2,
                                               ih2, 256, 256, 256, 256, 1, 0, 1);
    gemm_mma<<<dim3(2, GY), 256, SMEM_BYTES>>>(ih2, 256, nullptr, 0, iw3h, iw3m, nullptr, ib3,
                                               h0 + 1830, DPD, 256, 256, 256, 1, 0, 1);
    gemm_mma<<<dim3(4, GY), 256, SMEM_BYTES>>>(h0, DPD, nullptr, 0, gw1h, gw1m, nullptr, gb1,
                                               gh1, 512, 512, 1830, KP_G1, 1, 0, 1);
    gemm_mma<<<dim3(2, GY), 256, SMEM_BYTES>>>(gh1, 512, nullptr, 0, gw2h, gw2m, nullptr, gb2,
                                               gh2, 256, 256, 512, 512, 1, 0, 1);
    gate3_softmax<<<BSZ / 8, 256>>>(gh2, gw3, gb3, om);
    gemm_mma<<<dim3(4, GY), 256, SMEM_BYTES>>>(h0, DPD, nullptr, 0, ew1h, ew1m, om, eb1,
                                               e1, DH, DH, DPD, KP_E1, NE, 1, 1);
    gemm_mma<<<dim3(4, GY), 256, SMEM_BYTES>>>(e1, DH, nullptr, 0, ew2h, ew2m, om, eb2,
                                               e2, DH, DH, DH, DH, NE, 1, 1);
    gemm_mma<<<dim3(4, GY), 256, SMEM_BYTES>>>(e2, DH, nullptr, 0, ew3h, ew3m, om, eb3,
                                               e3, DH, DH, DH, DH, NE, 1, 1);
    gemm_mma<<<dim3(15, GY), 256, SMEM_BYTES>>>(e3, DH, nullptr, 0, hwh, hwm, nullptr, hbias,
                                                hd, DF, DF, DH, DH, 1, 0, 0);
    post_pose<<<(BSZ * 55 + 255) / 256, 256>>>(hd, out);
    post_copy<<<(BSZ * 1500 + 255) / 256, 256>>>(hd, out);
}

// round 7
// speedup vs baseline: 1.0254x; 1.0254x over previous
#include <cuda_runtime.h>
#include <cuda_bf16.h>
#include <math.h>
#include <stdint.h>

#define BSZ 4096
#define NE  6
#define DF  1830
#define DPD 2086
#define DH  512

// Kpad: multiples of 32
#define KP_I1 1056
#define KP_G1 1856
#define KP_E1 2112

#define BLK_BYTES 20480   // one (colTile,kChunk,expert) B block: hi 128x80B | mid 128x80B

// ---------------- scratch (device globals; no allocs allowed) ----------------
__device__ float g_h0 [BSZ*DPD];
__device__ float g_ih1[BSZ*256];
__device__ float g_ih2[BSZ*256];
__device__ float g_gh1[BSZ*512];
__device__ float g_gh2[BSZ*256];
__device__ float g_om [BSZ*NE];
__device__ float g_e1 [BSZ*DH];
__device__ float g_e2 [BSZ*DH];
__device__ float g_e3 [BSZ*DH];
__device__ float g_hd [BSZ*DF];
__device__ float g_hbias[DF];

// pre-packed weight blocks (chunk-exact smem images)
#define NB_I1 66      // 2 colTiles x 33 kChunks
#define NB_I2 16
#define NB_I3 16
#define NB_G1 232     // 4 x 58
#define NB_G2 32
#define NB_E1 1584    // 4 x 66 x 6
#define NB_E2 384     // 4 x 16 x 6
#define NB_E3 384
#define NB_HD 240     // 15 x 16
__device__ __align__(128) unsigned char s_bi1[(size_t)NB_I1*BLK_BYTES];
__device__ __align__(128) unsigned char s_bi2[(size_t)NB_I2*BLK_BYTES];
__device__ __align__(128) unsigned char s_bi3[(size_t)NB_I3*BLK_BYTES];
__device__ __align__(128) unsigned char s_bg1[(size_t)NB_G1*BLK_BYTES];
__device__ __align__(128) unsigned char s_bg2[(size_t)NB_G2*BLK_BYTES];
__device__ __align__(128) unsigned char s_be1[(size_t)NB_E1*BLK_BYTES];
__device__ __align__(128) unsigned char s_be2[(size_t)NB_E2*BLK_BYTES];
__device__ __align__(128) unsigned char s_be3[(size_t)NB_E3*BLK_BYTES];
__device__ __align__(128) unsigned char s_bhd[(size_t)NB_HD*BLK_BYTES];

__device__ __forceinline__ float elu1(float x) { return x > 0.f ? x : expm1f(x); }

__device__ __forceinline__ uint32_t smem_u32(const void* p) {
    uint32_t a;
    asm("{ .reg .u64 t; cvta.to.shared.u64 t, %1; cvt.u32.u64 %0, t; }" : "=r"(a) : "l"(p));
    return a;
}
__device__ __forceinline__ uint32_t pack_split(float x0, float x1, uint32_t& mid) {
    __nv_bfloat16 h0 = __float2bfloat16(x0);
    __nv_bfloat16 h1 = __float2bfloat16(x1);
    float r0 = x0 - __bfloat162float(h0);
    float r1 = x1 - __bfloat162float(h1);
    __nv_bfloat16 m0 = __float2bfloat16(r0);
    __nv_bfloat16 m1 = __float2bfloat16(r1);
    mid = ((uint32_t)__bfloat16_as_ushort(m1) << 16) | __bfloat16_as_ushort(m0);
    return ((uint32_t)__bfloat16_as_ushort(h1) << 16) | __bfloat16_as_ushort(h0);
}
__device__ __forceinline__ void ldm4(uint32_t& r0, uint32_t& r1, uint32_t& r2, uint32_t& r3,
                                     uint32_t addr) {
    asm volatile("ldmatrix.sync.aligned.m8n8.x4.shared.b16 {%0,%1,%2,%3}, [%4];"
                 : "=r"(r0), "=r"(r1), "=r"(r2), "=r"(r3) : "r"(addr));
}
__device__ __forceinline__ void mma16816(float* d, const uint32_t* a, uint32_t b0, uint32_t b1) {
    asm volatile("mma.sync.aligned.m16n8k16.row.col.f32.bf16.bf16.f32 "
                 "{%0,%1,%2,%3}, {%4,%5,%6,%7}, {%8,%9}, {%0,%1,%2,%3};"
                 : "+f"(d[0]), "+f"(d[1]), "+f"(d[2]), "+f"(d[3])
                 : "r"(a[0]), "r"(a[1]), "r"(a[2]), "r"(a[3]), "r"(b0), "r"(b1));
}
__device__ __forceinline__ void mbar_init(uint32_t m, uint32_t cnt) {
    asm volatile("mbarrier.init.shared.b64 [%0], %1;" :: "r"(m), "r"(cnt) : "memory");
}
__device__ __forceinline__ void mbar_expect_tx(uint32_t m, uint32_t bytes) {
    asm volatile("mbarrier.arrive.expect_tx.shared.b64 _, [%0], %1;"
                 :: "r"(m), "r"(bytes) : "memory");
}
__device__ __forceinline__ void bulk_g2s(uint32_t dst, const void* src, uint32_t bytes, uint32_t m) {
    asm volatile("cp.async.bulk.shared::cluster.global.mbarrier::complete_tx::bytes "
                 "[%0], [%1], %2, [%3];"
                 :: "r"(dst), "l"(src), "r"(bytes), "r"(m) : "memory");
}
__device__ __forceinline__ void mbar_wait(uint32_t m, uint32_t ph) {
    asm volatile("{\n\t.reg .pred P;\n\tWL%=:\n\t"
        "mbarrier.try_wait.parity.acquire.cta.shared::cta.b64 P, [%0], %1, 0x989680;\n\t"
        "@P bra.uni WD%=;\n\tbra.uni WL%=;\n\tWD%=:\n\t}"
        :: "r"(m), "r"(ph) : "memory");
}

// ---------------- smem layout ----------------
constexpr int OFF_OM   = 0;          // NE*128*4 = 3072
constexpr int OFF_AH   = 3072;       // 128 x 80B
constexpr int OFF_AM   = 13312;
constexpr int OFF_MBAR = 23552;      // 3 x 8B
constexpr int OFF_B    = 23616;      // 3 stages x 20480
constexpr int SMEM_BYTES = OFF_B + 3 * BLK_BYTES;   // 85056

// ---------------------------------------------------------------------------
// bf16x3 split GEMM on mma.sync; B blocks streamed via cp.async.bulk + mbarrier.
//   C[4096, Nw] = act( sum_e omega[:,e] * (A @ W_e) + bias )
// Wblk layout: [colTile][kChunk][expert] 20480B chunk-exact smem images.
// ---------------------------------------------------------------------------
__global__ void __launch_bounds__(256, 1) gemm_mma(
    const float* __restrict__ A, int lda,
    const float* __restrict__ A2, int K1,
    const unsigned char* __restrict__ Wblk,
    const float* __restrict__ omega,
    const float* __restrict__ bias,
    float* __restrict__ C, int ldc,
    int Nw, int K, int Kpad, int E, int blend, int doElu)
{
    extern __shared__ char smem[];
    const uint32_t sb = smem_u32(smem);
    float* omS = (float*)(smem + OFF_OM);

    const int tid  = threadIdx.x;
    const int lane = tid & 31, warp = tid >> 5;
    const int m_base = (warp & 3) * 32;
    const int n_base = (warp >> 2) * 64;
    const int rowBase = blockIdx.y * 128;
    const int colBase = blockIdx.x * 128;

    if (tid == 0) {
        mbar_init(sb + OFF_MBAR, 1);
        mbar_init(sb + OFF_MBAR + 8, 1);
        mbar_init(sb + OFF_MBAR + 16, 1);
        asm volatile("fence.proxy.async.shared::cta;" ::: "memory");
    }
    for (int i = tid; i < E * 128; i += 256) {
        int e = i >> 7, r = i & 127;
        omS[e * 128 + r] = omega ? omega[(size_t)(rowBase + r) * E + e] : 1.0f;
    }
    __syncthreads();

    float acc[2][8][4];
#pragma unroll
    for (int a = 0; a < 2; a++)
#pragma unroll
        for (int b = 0; b < 8; b++)
#pragma unroll
            for (int c = 0; c < 4; c++) acc[a][b][c] = 0.f;

    const int r  = tid >> 1, h = tid & 1;        // A staging: row, k-half
    const int row = rowBase + r;
    const int lm = lane & 15, lc = lane >> 4;    // ldmatrix A mapping
    const int g  = lane >> 3;
    const int b_row  = ((g >> 1) << 3) + (lane & 7);
    const int b_koff = (g & 1) << 4;

    const int nKC = Kpad >> 5;
    const int NC = nKC * E;
    const unsigned char* Wct = Wblk + (size_t)blockIdx.x * NC * BLK_BYTES;

    // one bulk copy per chunk
    auto issue = [&](int c) {
        uint32_t m = sb + OFF_MBAR + 8 * (c % 3);
        mbar_expect_tx(m, BLK_BYTES);
        bulk_g2s(sb + OFF_B + (c % 3) * BLK_BYTES, Wct + (size_t)c * BLK_BYTES, BLK_BYTES, m);
    };
    if (tid == 0) { issue(0); issue(1); }

    uint32_t aH[2][2][4], aM[2][2][4];           // [kh][m2][4]

    for (int c = 0; c < NC; c++) {
        const int e = c % E;
        mbar_wait(sb + OFF_MBAR + 8 * (c % 3), (c / 3) & 1);
        __syncthreads();

        if (e == 0) {
            // ---- A split for this k-chunk ----
            const int k0 = (c / E) << 5;
            float v[16];
#pragma unroll
            for (int j = 0; j < 16; j++) {
                int k = k0 + h * 16 + j;
                float x = 0.f;
                if (k < K) x = (A2 && k >= K1) ? A2[row * 3 + (k - K1)]
                                               : A[(size_t)row * lda + k];
                v[j] = x;
            }
            uint32_t hi[8], mi[8];
#pragma unroll
            for (int u = 0; u < 8; u++) hi[u] = pack_split(v[2*u], v[2*u+1], mi[u]);
            char* dH = smem + OFF_AH + r * 80 + h * 32;
            char* dM = smem + OFF_AM + r * 80 + h * 32;
            *(uint4*)dH        = make_uint4(hi[0], hi[1], hi[2], hi[3]);
            *(uint4*)(dH + 16) = make_uint4(hi[4], hi[5], hi[6], hi[7]);
            *(uint4*)dM        = make_uint4(mi[0], mi[1], mi[2], mi[3]);
            *(uint4*)(dM + 16) = make_uint4(mi[4], mi[5], mi[6], mi[7]);
            __syncthreads();
            // ---- hoist A fragments (reused across experts) ----
#pragma unroll
            for (int kh = 0; kh < 2; kh++)
#pragma unroll
                for (int m2 = 0; m2 < 2; m2++) {
                    uint32_t ad = (m_base + m2 * 16 + lm) * 80 + kh * 32 + lc * 16;
                    ldm4(aH[kh][m2][0], aH[kh][m2][1], aH[kh][m2][2], aH[kh][m2][3], sb + OFF_AH + ad);
                    ldm4(aM[kh][m2][0], aM[kh][m2][1], aM[kh][m2][2], aM[kh][m2][3], sb + OFF_AM + ad);
                }
        }

        // ---- MMA chunk into tmp, then omega-scale into acc ----
        float tmp[2][8][4];
#pragma unroll
        for (int a = 0; a < 2; a++)
#pragma unroll
            for (int b = 0; b < 8; b++)
#pragma unroll
                for (int cc = 0; cc < 4; cc++) tmp[a][b][cc] = 0.f;

        const uint32_t bhB = sb + OFF_B + (c % 3) * BLK_BYTES;
        const uint32_t bmB = bhB + 10240;
#pragma unroll
        for (int kh = 0; kh < 2; kh++) {
            uint32_t bh[4][4], bm[4][4];
#pragma unroll
            for (int ni = 0; ni < 4; ni++) {
                uint32_t bd = (n_base + ni * 16 + b_row) * 80 + kh * 32 + b_koff;
                ldm4(bh[ni][0], bh[ni][1], bh[ni][2], bh[ni][3], bhB + bd);
                ldm4(bm[ni][0], bm[ni][1], bm[ni][2], bm[ni][3], bmB + bd);
            }
#pragma unroll
            for (int ni = 0; ni < 4; ni++)
#pragma unroll
                for (int m2 = 0; m2 < 2; m2++) {
                    mma16816(tmp[m2][2*ni],   aH[kh][m2], bh[ni][0], bh[ni][1]);  // hi*hi
                    mma16816(tmp[m2][2*ni+1], aH[kh][m2], bh[ni][2], bh[ni][3]);
                    mma16816(tmp[m2][2*ni],   aH[kh][m2], bm[ni][0], bm[ni][1]);  // hi*mid
                    mma16816(tmp[m2][2*ni+1], aH[kh][m2], bm[ni][2], bm[ni][3]);
                    mma16816(tmp[m2][2*ni],   aM[kh][m2], bh[ni][0], bh[ni][1]);  // mid*hi
                    mma16816(tmp[m2][2*ni+1], aM[kh][m2], bh[ni][2], bh[ni][3]);
                }
        }
#pragma unroll
        for (int m2 = 0; m2 < 2; m2++) {
            float wA = omS[e * 128 + m_base + m2 * 16 + (lane >> 2)];
            float wB = omS[e * 128 + m_base + m2 * 16 + (lane >> 2) + 8];
#pragma unroll
            for (int nj = 0; nj < 8; nj++) {
                acc[m2][nj][0] += wA * tmp[m2][nj][0];
                acc[m2][nj][1] += wA * tmp[m2][nj][1];
                acc[m2][nj][2] += wB * tmp[m2][nj][2];
                acc[m2][nj][3] += wB * tmp[m2][nj][3];
            }
        }

        if (tid == 0 && c + 2 < NC) issue(c + 2);
    }

    // ---- epilogue ----
#pragma unroll
    for (int m2 = 0; m2 < 2; m2++) {
        int rlA = m_base + m2 * 16 + (lane >> 2);
        int rlB = rlA + 8;
#pragma unroll
        for (int nj = 0; nj < 8; nj++) {
            int n = colBase + n_base + nj * 8 + ((lane & 3) << 1);
            if (n >= Nw) continue;
            float bA0, bA1, bB0, bB1;
            if (blend) {
                bA0 = bA1 = bB0 = bB1 = 0.f;
                for (int e = 0; e < NE; e++) {
                    float be0 = bias[e * Nw + n], be1 = bias[e * Nw + n + 1];
                    bA0 += omS[e * 128 + rlA] * be0;  bA1 += omS[e * 128 + rlA] * be1;
                    bB0 += omS[e * 128 + rlB] * be0;  bB1 += omS[e * 128 + rlB] * be1;
                }
            } else {
                bA0 = bB0 = bias[n];
                bA1 = bB1 = bias[n + 1];
            }
            float v0 = acc[m2][nj][0] + bA0, v1 = acc[m2][nj][1] + bA1;
            float v2 = acc[m2][nj][2] + bB0, v3 = acc[m2][nj][3] + bB1;
            if (doElu) { v0 = elu1(v0); v1 = elu1(v1); v2 = elu1(v2); v3 = elu1(v3); }
            *(float2*)&C[(size_t)(rowBase + rlA) * ldc + n] = make_float2(v0, v1);
            *(float2*)&C[(size_t)(rowBase + rlB) * ldc + n] = make_float2(v2, v3);
        }
    }
}

// ---------------------------------------------------------------------------
// Weight prep: pack [E][K][Nw] fp32 -> chunk-exact block images
// block (ct, kc, e) -> 20480B: [hi 128 rows x 80B | mid 128 rows x 80B]
// ---------------------------------------------------------------------------
__global__ void prep_blocks(const float* __restrict__ W, unsigned char* __restrict__ dst,
                            int K, int Nw, int Kpad, int E) {
    __shared__ unsigned char tile[BLK_BYTES];
    const int nKC = Kpad >> 5;
    int blk = blockIdx.x;
    int e = blk % E;
    int kc = (blk / E) % nKC;
    int ct = blk / (E * nKC);
    int tid = threadIdx.x;
    uint4* t4 = (uint4*)tile;
    for (int i = tid; i < BLK_BYTES / 16; i += 256) t4[i] = make_uint4(0, 0, 0, 0);
    __syncthreads();
    for (int idx = tid; idx < 4096; idx += 256) {
        int k = idx >> 7, n = idx & 127;
        int gn = ct * 128 + n, gk = kc * 32 + k;
        float x = 0.f;
        if (gn < Nw && gk < K) x = W[((size_t)e * K + gk) * Nw + gn];
        __nv_bfloat16 hh = __float2bfloat16(x);
        __nv_bfloat16 mm = __float2bfloat16(x - __bfloat162float(hh));
        *(__nv_bfloat16*)(tile + n * 80 + k * 2) = hh;
        *(__nv_bfloat16*)(tile + 10240 + n * 80 + k * 2) = mm;
    }
    __syncthreads();
    uint4* d4 = (uint4*)(dst + (size_t)blk * BLK_BYTES);
    for (int i = tid; i < BLK_BYTES / 16; i += 256) d4[i] = t4[i];
}

__device__ __forceinline__ float head_w(const float* pw, const float* tw,
                                        const float* dw, const float* vw, int k, int n) {
    if (n < 330) return pw[k * 330 + n];
    if (n < 333) return tw[k * 3 + (n - 330)];
    if (n < 630) return dw[k * 297 + (n - 333)];
    return vw[(size_t)k * 1200 + (n - 630)];
}
__global__ void prep_blocks_hd(const float* __restrict__ pw, const float* __restrict__ tw,
                               const float* __restrict__ dw, const float* __restrict__ vw,
                               unsigned char* __restrict__ dst) {
    __shared__ unsigned char tile[BLK_BYTES];
    const int nKC = 16;
    int blk = blockIdx.x;
    int kc = blk % nKC;
    int ct = blk / nKC;
    int tid = threadIdx.x;
    uint4* t4 = (uint4*)tile;
    for (int i = tid; i < BLK_BYTES / 16; i += 256) t4[i] = make_uint4(0, 0, 0, 0);
    __syncthreads();
    for (int idx = tid; idx < 4096; idx += 256) {
        int k = idx >> 7, n = idx & 127;
        int gn = ct * 128 + n, gk = kc * 32 + k;
        float x = 0.f;
        if (gn < DF) x = head_w(pw, tw, dw, vw, gk, gn);
        __nv_bfloat16 hh = __float2bfloat16(x);
        __nv_bfloat16 mm = __float2bfloat16(x - __bfloat162float(hh));
        *(__nv_bfloat16*)(tile + n * 80 + k * 2) = hh;
        *(__nv_bfloat16*)(tile + 10240 + n * 80 + k * 2) = mm;
    }
    __syncthreads();
    uint4* d4 = (uint4*)(dst + (size_t)blk * BLK_BYTES);
    for (int i = tid; i < BLK_BYTES / 16; i += 256) d4[i] = t4[i];
}
__global__ void prep_hbias(const float* pb, const float* tb, const float* db, const float* vb,
                           float* out) {
    int n = blockIdx.x * 256 + threadIdx.x;
    if (n >= DF) return;
    float v;
    if (n < 330) v = pb[n];
    else if (n < 333) v = tb[n - 330];
    else if (n < 630) v = db[n - 333];
    else v = vb[n - 630];
    out[n] = v;
}

// ---------------------------------------------------------------------------
__global__ void assemble_frame(const float* __restrict__ rot, const float* __restrict__ tr,
                               const float* __restrict__ verts, const float* __restrict__ dists) {
    int idx = blockIdx.x * 256 + threadIdx.x;
    if (idx >= BSZ * DF) return;
    int b = idx / DF, c = idx % DF;
    float v;
    if (c < 330) {
        int j = c / 6, s = c % 6;
        v = rot[b * 495 + j * 9 + (s >> 1) * 3 + (s & 1)];
    } else if (c < 333) v = tr[b * 3 + (c - 330)];
    else if (c < 1533)  v = verts[b * 1200 + (c - 333)];
    else                v = dists[b * 297 + (c - 1533)];
    g_h0[(size_t)b * DPD + c] = v;
}

__global__ void gate3_softmax(const float* __restrict__ H, const float* __restrict__ W,
                              const float* __restrict__ b, float* __restrict__ om) {
    int warp = (blockIdx.x * blockDim.x + threadIdx.x) >> 5;
    int lane = threadIdx.x & 31;
    if (warp >= BSZ) return;
    float p[NE] = {};
    for (int k = lane; k < 256; k += 32) {
        float x = H[(size_t)warp * 256 + k];
#pragma unroll
        for (int e = 0; e < NE; e++) p[e] += x * W[k * NE + e];
    }
#pragma unroll
    for (int e = 0; e < NE; e++)
        for (int o = 16; o > 0; o >>= 1) p[e] += __shfl_down_sync(0xffffffffu, p[e], o);
    if (lane == 0) {
        float m = -1e30f;
#pragma unroll
        for (int e = 0; e < NE; e++) { p[e] += b[e]; m = fmaxf(m, p[e]); }
        float s = 0.f;
#pragma unroll
        for (int e = 0; e < NE; e++) { p[e] = expf(p[e] - m); s += p[e]; }
        float inv = 1.f / s;
#pragma unroll
        for (int e = 0; e < NE; e++) om[(size_t)warp * NE + e] = p[e] * inv;
    }
}

__global__ void post_pose(const float* __restrict__ hd, float* __restrict__ out) {
    int idx = blockIdx.x * 256 + threadIdx.x;
    if (idx >= BSZ * 55) return;
    int b = idx / 55, j = idx % 55;
    const float* p = hd + (size_t)b * DF + j * 6;
    float a1x = p[0], a2x = p[1], a1y = p[2], a2y = p[3], a1z = p[4], a2z = p[5];
    float inv = rsqrtf(a1x * a1x + a1y * a1y + a1z * a1z);
    float b1x = a1x * inv, b1y = a1y * inv, b1z = a1z * inv;
    float d = b1x * a2x + b1y * a2y + b1z * a2z;
    float cx = a2x - d * b1x, cy = a2y - d * b1y, cz = a2z - d * b1z;
    float inv2 = rsqrtf(cx * cx + cy * cy + cz * cz);
    float b2x = cx * inv2, b2y = cy * inv2, b2z = cz * inv2;
    float b3x = b1y * b2z - b1z * b2y;
    float b3y = b1z * b2x - b1x * b2z;
    float b3z = b1x * b2y - b1y * b2x;
    float* o = out + (size_t)b * 495 + j * 9;
    o[0] = b1x; o[1] = b2x; o[2] = b3x;
    o[3] = b1y; o[4] = b2y; o[5] = b3y;
    o[6] = b1z; o[7] = b2z; o[8] = b3z;
}

__global__ void post_copy(const float* __restrict__ hd, float* __restrict__ out) {
    const size_t base_t = (size_t)BSZ * 495;
    const size_t base_d = base_t + (size_t)BSZ * 3;
    const size_t base_v = base_d + (size_t)BSZ * 297;
    int idx = blockIdx.x * 256 + threadIdx.x;
    if (idx >= BSZ * 1500) return;
    int b = idx / 1500, c = idx % 1500;
    const float* row = hd + (size_t)b * DF;
    if (c < 3)        out[base_t + (size_t)b * 3 + c]            = row[330 + c];
    else if (c < 300) out[base_d + (size_t)b * 297 + (c - 3)]    = row[333 + (c - 3)];
    else              out[base_v + (size_t)b * 1200 + (c - 300)] = row[630 + (c - 300)];
}

// ---------------------------------------------------------------------------
extern "C" void kernel_launch(void* const* d_in, const int* in_sizes, int n_in,
                              void* d_out, int out_size) {
    const float* rot   = (const float*)d_in[0];
    const float* tr    = (const float*)d_in[1];
    const float* verts = (const float*)d_in[2];
    const float* dists = (const float*)d_in[3];
    const float* bps   = (const float*)d_in[4];
    const float* ogt   = (const float*)d_in[5];
    const float* iw1 = (const float*)d_in[6];  const float* ib1 = (const float*)d_in[7];
    const float* iw2 = (const float*)d_in[8];  const float* ib2 = (const float*)d_in[9];
    const float* iw3 = (const float*)d_in[10]; const float* ib3 = (const float*)d_in[11];
    const float* gw1 = (const float*)d_in[12]; const float* gb1 = (const float*)d_in[13];
    const float* gw2 = (const float*)d_in[14]; const float* gb2 = (const float*)d_in[15];
    const float* gw3 = (const float*)d_in[16]; const float* gb3 = (const float*)d_in[17];
    const float* ew1 = (const float*)d_in[18]; const float* eb1 = (const float*)d_in[19];
    const float* ew2 = (const float*)d_in[20]; const float* eb2 = (const float*)d_in[21];
    const float* ew3 = (const float*)d_in[22]; const float* eb3 = (const float*)d_in[23];
    const float* pw  = (const float*)d_in[24]; const float* pb  = (const float*)d_in[25];
    const float* tw  = (const float*)d_in[26]; const float* tb  = (const float*)d_in[27];
    const float* vw  = (const float*)d_in[28]; const float* vb  = (const float*)d_in[29];
    const float* dw  = (const float*)d_in[30]; const float* db  = (const float*)d_in[31];
    float* out = (float*)d_out;

    cudaFuncSetAttribute(gemm_mma, cudaFuncAttributeMaxDynamicSharedMemorySize, SMEM_BYTES);

    float *h0, *ih1, *ih2, *gh1, *gh2, *om, *e1, *e2, *e3, *hd, *hbias;
    cudaGetSymbolAddress((void**)&h0,  g_h0);
    cudaGetSymbolAddress((void**)&ih1, g_ih1);
    cudaGetSymbolAddress((void**)&ih2, g_ih2);
    cudaGetSymbolAddress((void**)&gh1, g_gh1);
    cudaGetSymbolAddress((void**)&gh2, g_gh2);
    cudaGetSymbolAddress((void**)&om,  g_om);
    cudaGetSymbolAddress((void**)&e1,  g_e1);
    cudaGetSymbolAddress((void**)&e2,  g_e2);
    cudaGetSymbolAddress((void**)&e3,  g_e3);
    cudaGetSymbolAddress((void**)&hd,  g_hd);
    cudaGetSymbolAddress((void**)&hbias, g_hbias);
    unsigned char *bi1,*bi2,*bi3,*bg1,*bg2,*be1,*be2,*be3,*bhd;
    cudaGetSymbolAddress((void**)&bi1, s_bi1);
    cudaGetSymbolAddress((void**)&bi2, s_bi2);
    cudaGetSymbolAddress((void**)&bi3, s_bi3);
    cudaGetSymbolAddress((void**)&bg1, s_bg1);
    cudaGetSymbolAddress((void**)&bg2, s_bg2);
    cudaGetSymbolAddress((void**)&be1, s_be1);
    cudaGetSymbolAddress((void**)&be2, s_be2);
    cudaGetSymbolAddress((void**)&be3, s_be3);
    cudaGetSymbolAddress((void**)&bhd, s_bhd);

    // weight packing (chunk-exact block images)
    prep_blocks<<<NB_I1, 256>>>(iw1, bi1, 1027, 256, KP_I1, 1);
    prep_blocks<<<NB_I2, 256>>>(iw2, bi2, 256, 256, 256, 1);
    prep_blocks<<<NB_I3, 256>>>(iw3, bi3, 256, 256, 256, 1);
    prep_blocks<<<NB_G1, 256>>>(gw1, bg1, 1830, 512, KP_G1, 1);
    prep_blocks<<<NB_G2, 256>>>(gw2, bg2, 512, 256, 512, 1);
    prep_blocks<<<NB_E1, 256>>>(ew1, be1, 2086, 512, KP_E1, NE);
    prep_blocks<<<NB_E2, 256>>>(ew2, be2, 512, 512, 512, NE);
    prep_blocks<<<NB_E3, 256>>>(ew3, be3, 512, 512, 512, NE);
    prep_blocks_hd<<<NB_HD, 256>>>(pw, tw, dw, vw, bhd);
    prep_hbias<<<8, 256>>>(pb, tb, db, vb, hbias);

    assemble_frame<<<(BSZ * DF + 255) / 256, 256>>>(rot, tr, verts, dists);

    const int GY = BSZ / 128;  // 32
    gemm_mma<<<dim3(2, GY), 256, SMEM_BYTES>>>(bps, 1024, ogt, 1024, bi1, nullptr, ib1,
                                               ih1, 256, 256, 1027, KP_I1, 1, 0, 1);
    gemm_mma<<<dim3(2, GY), 256, SMEM_BYTES>>>(ih1, 256, nullptr, 0, bi2, nullptr, ib2,
                                               ih2, 256, 256, 256, 256, 1, 0, 1);
    gemm_mma<<<dim3(2, GY), 256, SMEM_BYTES>>>(ih2, 256, nullptr, 0, bi3, nullptr, ib3,
                                               h0 + 1830, DPD, 256, 256, 256, 1, 0, 1);
    gemm_mma<<<dim3(4, GY), 256, SMEM_BYTES>>>(h0, DPD, nullptr, 0, bg1, nullptr, gb1,
                                               gh1, 512, 512, 1830, KP_G1, 1, 0, 1);
    gemm_mma<<<dim3(2, GY), 256, SMEM_BYTES>>>(gh1, 512, nullptr, 0, bg2, nullptr, gb2,
                                               gh2, 256, 256, 512, 512, 1, 0, 1);
    gate3_softmax<<<BSZ / 8, 256>>>(gh2, gw3, gb3, om);
    gemm_mma<<<dim3(4, GY), 256, SMEM_BYTES>>>(h0, DPD, nullptr, 0, be1, om, eb1,
                                               e1, DH, DH, DPD, KP_E1, NE, 1, 1);
    gemm_mma<<<dim3(4, GY), 256, SMEM_BYTES>>>(e1, DH, nullptr, 0, be2, om, eb2,
                                               e2, DH, DH, DH, DH, NE, 1, 1);
    gemm_mma<<<dim3(4, GY), 256, SMEM_BYTES>>>(e2, DH, nullptr, 0, be3, om, eb3,
                                               e3, DH, DH, DH, DH, NE, 1, 1);
    gemm_mma<<<dim3(15, GY), 256, SMEM_BYTES>>>(e3, DH, nullptr, 0, bhd, nullptr, hbias,
                                                hd, DF, DF, DH, DH, 1, 0, 0);
    post_pose<<<(BSZ * 55 + 255) / 256, 256>>>(hd, out);
    post_copy<<<(BSZ * 1500 + 255) / 256, 256>>>(hd, out);
}

// round 8
// speedup vs baseline: 1.0258x; 1.0003x over previous
#include <cuda_runtime.h>
#include <cuda_bf16.h>
#include <math.h>
#include <stdint.h>

#define BSZ 4096
#define NE  6
#define DF  1830
#define DPD 2086
#define DH  512

// Kpad: multiples of 32
#define KP_I1 1056
#define KP_G1 1856
#define KP_E1 2112

#define BLK_BYTES 20480   // one (colTile,kChunk,expert) B block: hi 128x80B | mid 128x80B

// ---------------- scratch (device globals; no allocs allowed) ----------------
__device__ float g_h0 [BSZ*DPD];
__device__ float g_ih1[BSZ*256];
__device__ float g_ih2[BSZ*256];
__device__ float g_gh1[BSZ*512];
__device__ float g_gh2[BSZ*256];
__device__ float g_om [BSZ*NE];
__device__ float g_e1 [BSZ*DH];
__device__ float g_e2 [BSZ*DH];
__device__ float g_e3 [BSZ*DH];
__device__ float g_hd [BSZ*DF];
__device__ float g_hbias[DF];

// pre-packed weight blocks (chunk-exact smem images)
#define NB_I1 66      // 2 colTiles x 33 kChunks
#define NB_I2 16
#define NB_I3 16
#define NB_G1 232     // 4 x 58
#define NB_G2 32
#define NB_E1 1584    // 4 x 66 x 6
#define NB_E2 384     // 4 x 16 x 6
#define NB_E3 384
#define NB_HD 240     // 15 x 16
__device__ __align__(128) unsigned char s_bi1[(size_t)NB_I1*BLK_BYTES];
__device__ __align__(128) unsigned char s_bi2[(size_t)NB_I2*BLK_BYTES];
__device__ __align__(128) unsigned char s_bi3[(size_t)NB_I3*BLK_BYTES];
__device__ __align__(128) unsigned char s_bg1[(size_t)NB_G1*BLK_BYTES];
__device__ __align__(128) unsigned char s_bg2[(size_t)NB_G2*BLK_BYTES];
__device__ __align__(128) unsigned char s_be1[(size_t)NB_E1*BLK_BYTES];
__device__ __align__(128) unsigned char s_be2[(size_t)NB_E2*BLK_BYTES];
__device__ __align__(128) unsigned char s_be3[(size_t)NB_E3*BLK_BYTES];
__device__ __align__(128) unsigned char s_bhd[(size_t)NB_HD*BLK_BYTES];

__device__ __forceinline__ float elu1(float x) { return x > 0.f ? x : expm1f(x); }

__device__ __forceinline__ uint32_t smem_u32(const void* p) {
    uint32_t a;
    asm("{ .reg .u64 t; cvta.to.shared.u64 t, %1; cvt.u32.u64 %0, t; }" : "=r"(a) : "l"(p));
    return a;
}
__device__ __forceinline__ uint32_t pack_split(float x0, float x1, uint32_t& mid) {
    __nv_bfloat16 h0 = __float2bfloat16(x0);
    __nv_bfloat16 h1 = __float2bfloat16(x1);
    float r0 = x0 - __bfloat162float(h0);
    float r1 = x1 - __bfloat162float(h1);
    __nv_bfloat16 m0 = __float2bfloat16(r0);
    __nv_bfloat16 m1 = __float2bfloat16(r1);
    mid = ((uint32_t)__bfloat16_as_ushort(m1) << 16) | __bfloat16_as_ushort(m0);
    return ((uint32_t)__bfloat16_as_ushort(h1) << 16) | __bfloat16_as_ushort(h0);
}
__device__ __forceinline__ void ldm4(uint32_t& r0, uint32_t& r1, uint32_t& r2, uint32_t& r3,
                                     uint32_t addr) {
    asm volatile("ldmatrix.sync.aligned.m8n8.x4.shared.b16 {%0,%1,%2,%3}, [%4];"
                 : "=r"(r0), "=r"(r1), "=r"(r2), "=r"(r3) : "r"(addr));
}
// accumulate form: d += a*b
__device__ __forceinline__ void mma16816(float* d, const uint32_t* a, uint32_t b0, uint32_t b1) {
    asm volatile("mma.sync.aligned.m16n8k16.row.col.f32.bf16.bf16.f32 "
                 "{%0,%1,%2,%3}, {%4,%5,%6,%7}, {%8,%9}, {%0,%1,%2,%3};"
                 : "+f"(d[0]), "+f"(d[1]), "+f"(d[2]), "+f"(d[3])
                 : "r"(a[0]), "r"(a[1]), "r"(a[2]), "r"(a[3]), "r"(b0), "r"(b1));
}
// init form: d = a*b + 0   (breaks the RAW chain on d, kills tmp zeroing)
__device__ __forceinline__ void mma16816_z(float* d, const uint32_t* a, uint32_t b0, uint32_t b1) {
    asm volatile("mma.sync.aligned.m16n8k16.row.col.f32.bf16.bf16.f32 "
                 "{%0,%1,%2,%3}, {%4,%5,%6,%7}, {%8,%9}, {%10,%11,%12,%13};"
                 : "=f"(d[0]), "=f"(d[1]), "=f"(d[2]), "=f"(d[3])
                 : "r"(a[0]), "r"(a[1]), "r"(a[2]), "r"(a[3]), "r"(b0), "r"(b1),
                   "f"(0.f), "f"(0.f), "f"(0.f), "f"(0.f));
}
__device__ __forceinline__ void mbar_init(uint32_t m, uint32_t cnt) {
    asm volatile("mbarrier.init.shared.b64 [%0], %1;" :: "r"(m), "r"(cnt) : "memory");
}
__device__ __forceinline__ void mbar_expect_tx(uint32_t m, uint32_t bytes) {
    asm volatile("mbarrier.arrive.expect_tx.shared.b64 _, [%0], %1;"
                 :: "r"(m), "r"(bytes) : "memory");
}
__device__ __forceinline__ void bulk_g2s(uint32_t dst, const void* src, uint32_t bytes, uint32_t m) {
    asm volatile("cp.async.bulk.shared::cluster.global.mbarrier::complete_tx::bytes "
                 "[%0], [%1], %2, [%3];"
                 :: "r"(dst), "l"(src), "r"(bytes), "r"(m) : "memory");
}
__device__ __forceinline__ void mbar_wait(uint32_t m, uint32_t ph) {
    asm volatile("{\n\t.reg .pred P;\n\tWL%=:\n\t"
        "mbarrier.try_wait.parity.acquire.cta.shared::cta.b64 P, [%0], %1, 0x989680;\n\t"
        "@P bra.uni WD%=;\n\tbra.uni WL%=;\n\tWD%=:\n\t}"
        :: "r"(m), "r"(ph) : "memory");
}

// ---------------- smem layout ----------------
constexpr int OFF_OM   = 0;          // NE*128*4 = 3072
constexpr int OFF_AH   = 3072;       // 128 x 80B
constexpr int OFF_AM   = 13312;
constexpr int OFF_MBAR = 23552;      // 3 x 8B
constexpr int OFF_B    = 23616;      // 3 stages x 20480
constexpr int SMEM_BYTES = OFF_B + 3 * BLK_BYTES;   // 85056

// ---------------------------------------------------------------------------
// bf16x3 split GEMM on mma.sync; B via cp.async.bulk ring; term-major MMA
// passes so RAW deps on any accumulator are >=16 MMAs apart.
//   C[4096, Nw] = act( sum_e omega[:,e] * (A @ W_e) + bias )
// ---------------------------------------------------------------------------
__global__ void __launch_bounds__(256, 1) gemm_mma(
    const float* __restrict__ A, int lda,
    const float* __restrict__ A2, int K1,
    const unsigned char* __restrict__ Wblk,
    const float* __restrict__ omega,
    const float* __restrict__ bias,
    float* __restrict__ C, int ldc,
    int Nw, int K, int Kpad, int E, int blend, int doElu)
{
    extern __shared__ char smem[];
    const uint32_t sb = smem_u32(smem);
    float* omS = (float*)(smem + OFF_OM);

    const int tid  = threadIdx.x;
    const int lane = tid & 31, warp = tid >> 5;
    const int m_base = (warp & 3) * 32;
    const int n_base = (warp >> 2) * 64;
    const int rowBase = blockIdx.y * 128;
    const int colBase = blockIdx.x * 128;

    if (tid == 0) {
        mbar_init(sb + OFF_MBAR, 1);
        mbar_init(sb + OFF_MBAR + 8, 1);
        mbar_init(sb + OFF_MBAR + 16, 1);
        asm volatile("fence.proxy.async.shared::cta;" ::: "memory");
    }
    for (int i = tid; i < E * 128; i += 256) {
        int e = i >> 7, r = i & 127;
        omS[e * 128 + r] = omega ? omega[(size_t)(rowBase + r) * E + e] : 1.0f;
    }
    __syncthreads();

    float acc[2][8][4];
#pragma unroll
    for (int a = 0; a < 2; a++)
#pragma unroll
        for (int b = 0; b < 8; b++)
#pragma unroll
            for (int c = 0; c < 4; c++) acc[a][b][c] = 0.f;

    const int r  = tid >> 1, h = tid & 1;        // A staging: row, k-half
    const int row = rowBase + r;
    const int lm = lane & 15, lc = lane >> 4;    // ldmatrix A mapping
    const int g  = lane >> 3;
    const int b_row  = ((g >> 1) << 3) + (lane & 7);
    const int b_koff = (g & 1) << 4;

    const int nKC = Kpad >> 5;
    const int NC = nKC * E;
    const unsigned char* Wct = Wblk + (size_t)blockIdx.x * NC * BLK_BYTES;

    auto issue = [&](int c) {
        uint32_t m = sb + OFF_MBAR + 8 * (c % 3);
        mbar_expect_tx(m, BLK_BYTES);
        bulk_g2s(sb + OFF_B + (c % 3) * BLK_BYTES, Wct + (size_t)c * BLK_BYTES, BLK_BYTES, m);
    };
    if (tid == 0) { issue(0); issue(1); }

    uint32_t aH[2][2][4], aM[2][2][4];           // [kh][m2][4]

    for (int c = 0; c < NC; c++) {
        const int e = c % E;
        mbar_wait(sb + OFF_MBAR + 8 * (c % 3), (c / 3) & 1);
        __syncthreads();

        if (e == 0) {
            // ---- A split for this k-chunk ----
            const int k0 = (c / E) << 5;
            float v[16];
#pragma unroll
            for (int j = 0; j < 16; j++) {
                int k = k0 + h * 16 + j;
                float x = 0.f;
                if (k < K) x = (A2 && k >= K1) ? A2[row * 3 + (k - K1)]
                                               : A[(size_t)row * lda + k];
                v[j] = x;
            }
            uint32_t hi[8], mi[8];
#pragma unroll
            for (int u = 0; u < 8; u++) hi[u] = pack_split(v[2*u], v[2*u+1], mi[u]);
            char* dH = smem + OFF_AH + r * 80 + h * 32;
            char* dM = smem + OFF_AM + r * 80 + h * 32;
            *(uint4*)dH        = make_uint4(hi[0], hi[1], hi[2], hi[3]);
            *(uint4*)(dH + 16) = make_uint4(hi[4], hi[5], hi[6], hi[7]);
            *(uint4*)dM        = make_uint4(mi[0], mi[1], mi[2], mi[3]);
            *(uint4*)(dM + 16) = make_uint4(mi[4], mi[5], mi[6], mi[7]);
            __syncthreads();
            // ---- hoist A fragments (reused across experts) ----
#pragma unroll
            for (int kh = 0; kh < 2; kh++)
#pragma unroll
                for (int m2 = 0; m2 < 2; m2++) {
                    uint32_t ad = (m_base + m2 * 16 + lm) * 80 + kh * 32 + lc * 16;
                    ldm4(aH[kh][m2][0], aH[kh][m2][1], aH[kh][m2][2], aH[kh][m2][3], sb + OFF_AH + ad);
                    ldm4(aM[kh][m2][0], aM[kh][m2][1], aM[kh][m2][2], aM[kh][m2][3], sb + OFF_AM + ad);
                }
        }

        // ---- MMA chunk into tmp (term-major passes, 16-deep dep distance) ----
        float tmp[2][8][4];
        const uint32_t bhB = sb + OFF_B + (c % 3) * BLK_BYTES;
        const uint32_t bmB = bhB + 10240;
#pragma unroll
        for (int kh = 0; kh < 2; kh++) {
            uint32_t bh[4][4], bm[4][4];
#pragma unroll
            for (int ni = 0; ni < 4; ni++) {
                uint32_t bd = (n_base + ni * 16 + b_row) * 80 + kh * 32 + b_koff;
                ldm4(bh[ni][0], bh[ni][1], bh[ni][2], bh[ni][3], bhB + bd);
                ldm4(bm[ni][0], bm[ni][1], bm[ni][2], bm[ni][3], bmB + bd);
            }
            // pass 1: hi*hi  (kh==0: init tmp, no zero MOVs)
            if (kh == 0) {
#pragma unroll
                for (int ni = 0; ni < 4; ni++)
#pragma unroll
                    for (int m2 = 0; m2 < 2; m2++) {
                        mma16816_z(tmp[m2][2*ni],   aH[0][m2], bh[ni][0], bh[ni][1]);
                        mma16816_z(tmp[m2][2*ni+1], aH[0][m2], bh[ni][2], bh[ni][3]);
                    }
            } else {
#pragma unroll
                for (int ni = 0; ni < 4; ni++)
#pragma unroll
                    for (int m2 = 0; m2 < 2; m2++) {
                        mma16816(tmp[m2][2*ni],   aH[1][m2], bh[ni][0], bh[ni][1]);
                        mma16816(tmp[m2][2*ni+1], aH[1][m2], bh[ni][2], bh[ni][3]);
                    }
            }
            // pass 2: hi*mid
#pragma unroll
            for (int ni = 0; ni < 4; ni++)
#pragma unroll
                for (int m2 = 0; m2 < 2; m2++) {
                    mma16816(tmp[m2][2*ni],   aH[kh][m2], bm[ni][0], bm[ni][1]);
                    mma16816(tmp[m2][2*ni+1], aH[kh][m2], bm[ni][2], bm[ni][3]);
                }
            // pass 3: mid*hi
#pragma unroll
            for (int ni = 0; ni < 4; ni++)
#pragma unroll
                for (int m2 = 0; m2 < 2; m2++) {
                    mma16816(tmp[m2][2*ni],   aM[kh][m2], bh[ni][0], bh[ni][1]);
                    mma16816(tmp[m2][2*ni+1], aM[kh][m2], bh[ni][2], bh[ni][3]);
                }
        }
#pragma unroll
        for (int m2 = 0; m2 < 2; m2++) {
            float wA = omS[e * 128 + m_base + m2 * 16 + (lane >> 2)];
            float wB = omS[e * 128 + m_base + m2 * 16 + (lane >> 2) + 8];
#pragma unroll
            for (int nj = 0; nj < 8; nj++) {
                acc[m2][nj][0] += wA * tmp[m2][nj][0];
                acc[m2][nj][1] += wA * tmp[m2][nj][1];
                acc[m2][nj][2] += wB * tmp[m2][nj][2];
                acc[m2][nj][3] += wB * tmp[m2][nj][3];
            }
        }

        if (tid == 0 && c + 2 < NC) issue(c + 2);
    }

    // ---- epilogue ----
#pragma unroll
    for (int m2 = 0; m2 < 2; m2++) {
        int rlA = m_base + m2 * 16 + (lane >> 2);
        int rlB = rlA + 8;
#pragma unroll
        for (int nj = 0; nj < 8; nj++) {
            int n = colBase + n_base + nj * 8 + ((lane & 3) << 1);
            if (n >= Nw) continue;
            float bA0, bA1, bB0, bB1;
            if (blend) {
                bA0 = bA1 = bB0 = bB1 = 0.f;
                for (int e = 0; e < NE; e++) {
                    float be0 = bias[e * Nw + n], be1 = bias[e * Nw + n + 1];
                    bA0 += omS[e * 128 + rlA] * be0;  bA1 += omS[e * 128 + rlA] * be1;
                    bB0 += omS[e * 128 + rlB] * be0;  bB1 += omS[e * 128 + rlB] * be1;
                }
            } else {
                bA0 = bB0 = bias[n];
                bA1 = bB1 = bias[n + 1];
            }
            float v0 = acc[m2][nj][0] + bA0, v1 = acc[m2][nj][1] + bA1;
            float v2 = acc[m2][nj][2] + bB0, v3 = acc[m2][nj][3] + bB1;
            if (doElu) { v0 = elu1(v0); v1 = elu1(v1); v2 = elu1(v2); v3 = elu1(v3); }
            *(float2*)&C[(size_t)(rowBase + rlA) * ldc + n] = make_float2(v0, v1);
            *(float2*)&C[(size_t)(rowBase + rlB) * ldc + n] = make_float2(v2, v3);
        }
    }
}

// ---------------------------------------------------------------------------
// Weight prep: pack [E][K][Nw] fp32 -> chunk-exact block images
// ---------------------------------------------------------------------------
__global__ void prep_blocks(const float* __restrict__ W, unsigned char* __restrict__ dst,
                            int K, int Nw, int Kpad, int E) {
    __shared__ unsigned char tile[BLK_BYTES];
    const int nKC = Kpad >> 5;
    int blk = blockIdx.x;
    int e = blk % E;
    int kc = (blk / E) % nKC;
    int ct = blk / (E * nKC);
    int tid = threadIdx.x;
    uint4* t4 = (uint4*)tile;
    for (int i = tid; i < BLK_BYTES / 16; i += 256) t4[i] = make_uint4(0, 0, 0, 0);
    __syncthreads();
    for (int idx = tid; idx < 4096; idx += 256) {
        int k = idx >> 7, n = idx & 127;
        int gn = ct * 128 + n, gk = kc * 32 + k;
        float x = 0.f;
        if (gn < Nw && gk < K) x = W[((size_t)e * K + gk) * Nw + gn];
        __nv_bfloat16 hh = __float2bfloat16(x);
        __nv_bfloat16 mm = __float2bfloat16(x - __bfloat162float(hh));
        *(__nv_bfloat16*)(tile + n * 80 + k * 2) = hh;
        *(__nv_bfloat16*)(tile + 10240 + n * 80 + k * 2) = mm;
    }
    __syncthreads();
    uint4* d4 = (uint4*)(dst + (size_t)blk * BLK_BYTES);
    for (int i = tid; i < BLK_BYTES / 16; i += 256) d4[i] = t4[i];
}

__device__ __forceinline__ float head_w(const float* pw, const float* tw,
                                        const float* dw, const float* vw, int k, int n) {
    if (n < 330) return pw[k * 330 + n];
    if (n < 333) return tw[k * 3 + (n - 330)];
    if (n < 630) return dw[k * 297 + (n - 333)];
    return vw[(size_t)k * 1200 + (n - 630)];
}
__global__ void prep_blocks_hd(const float* __restrict__ pw, const float* __restrict__ tw,
                               const float* __restrict__ dw, const float* __restrict__ vw,
                               unsigned char* __restrict__ dst) {
    __shared__ unsigned char tile[BLK_BYTES];
    const int nKC = 16;
    int blk = blockIdx.x;
    int kc = blk % nKC;
    int ct = blk / nKC;
    int tid = threadIdx.x;
    uint4* t4 = (uint4*)tile;
    for (int i = tid; i < BLK_BYTES / 16; i += 256) t4[i] = make_uint4(0, 0, 0, 0);
    __syncthreads();
    for (int idx = tid; idx < 4096; idx += 256) {
        int k = idx >> 7, n = idx & 127;
        int gn = ct * 128 + n, gk = kc * 32 + k;
        float x = 0.f;
        if (gn < DF) x = head_w(pw, tw, dw, vw, gk, gn);
        __nv_bfloat16 hh = __float2bfloat16(x);
        __nv_bfloat16 mm = __float2bfloat16(x - __bfloat162float(hh));
        *(__nv_bfloat16*)(tile + n * 80 + k * 2) = hh;
        *(__nv_bfloat16*)(tile + 10240 + n * 80 + k * 2) = mm;
    }
    __syncthreads();
    uint4* d4 = (uint4*)(dst + (size_t)blk * BLK_BYTES);
    for (int i = tid; i < BLK_BYTES / 16; i += 256) d4[i] = t4[i];
}
__global__ void prep_hbias(const float* pb, const float* tb, const float* db, const float* vb,
                           float* out) {
    int n = blockIdx.x * 256 + threadIdx.x;
    if (n >= DF) return;
    float v;
    if (n < 330) v = pb[n];
    else if (n < 333) v = tb[n - 330];
    else if (n < 630) v = db[n - 333];
    else v = vb[n - 630];
    out[n] = v;
}

// ---------------------------------------------------------------------------
__global__ void assemble_frame(const float* __restrict__ rot, const float* __restrict__ tr,
                               const float* __restrict__ verts, const float* __restrict__ dists) {
    int idx = blockIdx.x * 256 + threadIdx.x;
    if (idx >= BSZ * DF) return;
    int b = idx / DF, c = idx % DF;
    float v;
    if (c < 330) {
        int j = c / 6, s = c % 6;
        v = rot[b * 495 + j * 9 + (s >> 1) * 3 + (s & 1)];
    } else if (c < 333) v = tr[b * 3 + (c - 330)];
    else if (c < 1533)  v = verts[b * 1200 + (c - 333)];
    else                v = dists[b * 297 + (c - 1533)];
    g_h0[(size_t)b * DPD + c] = v;
}

__global__ void gate3_softmax(const float* __restrict__ H, const float* __restrict__ W,
                              const float* __restrict__ b, float* __restrict__ om) {
    int warp = (blockIdx.x * blockDim.x + threadIdx.x) >> 5;
    int lane = threadIdx.x & 31;
    if (warp >= BSZ) return;
    float p[NE] = {};
    for (int k = lane; k < 256; k += 32) {
        float x = H[(size_t)warp * 256 + k];
#pragma unroll
        for (int e = 0; e < NE; e++) p[e] += x * W[k * NE + e];
    }
#pragma unroll
    for (int e = 0; e < NE; e++)
        for (int o = 16; o > 0; o >>= 1) p[e] += __shfl_down_sync(0xffffffffu, p[e], o);
    if (lane == 0) {
        float m = -1e30f;
#pragma unroll
        for (int e = 0; e < NE; e++) { p[e] += b[e]; m = fmaxf(m, p[e]); }
        float s = 0.f;
#pragma unroll
        for (int e = 0; e < NE; e++) { p[e] = expf(p[e] - m); s += p[e]; }
        float inv = 1.f / s;
#pragma unroll
        for (int e = 0; e < NE; e++) om[(size_t)warp * NE + e] = p[e] * inv;
    }
}

__global__ void post_pose(const float* __restrict__ hd, float* __restrict__ out) {
    int idx = blockIdx.x * 256 + threadIdx.x;
    if (idx >= BSZ * 55) return;
    int b = idx / 55, j = idx % 55;
    const float* p = hd + (size_t)b * DF + j * 6;
    float a1x = p[0], a2x = p[1], a1y = p[2], a2y = p[3], a1z = p[4], a2z = p[5];
    float inv = rsqrtf(a1x * a1x + a1y * a1y + a1z * a1z);
    float b1x = a1x * inv, b1y = a1y * inv, b1z = a1z * inv;
    float d = b1x * a2x + b1y * a2y + b1z * a2z;
    float cx = a2x - d * b1x, cy = a2y - d * b1y, cz = a2z - d * b1z;
    float inv2 = rsqrtf(cx * cx + cy * cy + cz * cz);
    float b2x = cx * inv2, b2y = cy * inv2, b2z = cz * inv2;
    float b3x = b1y * b2z - b1z * b2y;
    float b3y = b1z * b2x - b1x * b2z;
    float b3z = b1x * b2y - b1y * b2x;
    float* o = out + (size_t)b * 495 + j * 9;
    o[0] = b1x; o[1] = b2x; o[2] = b3x;
    o[3] = b1y; o[4] = b2y; o[5] = b3y;
    o[6] = b1z; o[7] = b2z; o[8] = b3z;
}

__global__ void post_copy(const float* __restrict__ hd, float* __restrict__ out) {
    const size_t base_t = (size_t)BSZ * 495;
    const size_t base_d = base_t + (size_t)BSZ * 3;
    const size_t base_v = base_d + (size_t)BSZ * 297;
    int idx = blockIdx.x * 256 + threadIdx.x;
    if (idx >= BSZ * 1500) return;
    int b = idx / 1500, c = idx % 1500;
    const float* row = hd + (size_t)b * DF;
    if (c < 3)        out[base_t + (size_t)b * 3 + c]            = row[330 + c];
    else if (c < 300) out[base_d + (size_t)b * 297 + (c - 3)]    = row[333 + (c - 3)];
    else              out[base_v + (size_t)b * 1200 + (c - 300)] = row[630 + (c - 300)];
}

// ---------------------------------------------------------------------------
extern "C" void kernel_launch(void* const* d_in, const int* in_sizes, int n_in,
                              void* d_out, int out_size) {
    const float* rot   = (const float*)d_in[0];
    const float* tr    = (const float*)d_in[1];
    const float* verts = (const float*)d_in[2];
    const float* dists = (const float*)d_in[3];
    const float* bps   = (const float*)d_in[4];
    const float* ogt   = (const float*)d_in[5];
    const float* iw1 = (const float*)d_in[6];  const float* ib1 = (const float*)d_in[7];
    const float* iw2 = (const float*)d_in[8];  const float* ib2 = (const float*)d_in[9];
    const float* iw3 = (const float*)d_in[10]; const float* ib3 = (const float*)d_in[11];
    const float* gw1 = (const float*)d_in[12]; const float* gb1 = (const float*)d_in[13];
    const float* gw2 = (const float*)d_in[14]; const float* gb2 = (const float*)d_in[15];
    const float* gw3 = (const float*)d_in[16]; const float* gb3 = (const float*)d_in[17];
    const float* ew1 = (const float*)d_in[18]; const float* eb1 = (const float*)d_in[19];
    const float* ew2 = (const float*)d_in[20]; const float* eb2 = (const float*)d_in[21];
    const float* ew3 = (const float*)d_in[22]; const float* eb3 = (const float*)d_in[23];
    const float* pw  = (const float*)d_in[24]; const float* pb  = (const float*)d_in[25];
    const float* tw  = (const float*)d_in[26]; const float* tb  = (const float*)d_in[27];
    const float* vw  = (const float*)d_in[28]; const float* vb  = (const float*)d_in[29];
    const float* dw  = (const float*)d_in[30]; const float* db  = (const float*)d_in[31];
    float* out = (float*)d_out;

    cudaFuncSetAttribute(gemm_mma, cudaFuncAttributeMaxDynamicSharedMemorySize, SMEM_BYTES);

    float *h0, *ih1, *ih2, *gh1, *gh2, *om, *e1, *e2, *e3, *hd, *hbias;
    cudaGetSymbolAddress((void**)&h0,  g_h0);
    cudaGetSymbolAddress((void**)&ih1, g_ih1);
    cudaGetSymbolAddress((void**)&ih2, g_ih2);
    cudaGetSymbolAddress((void**)&gh1, g_gh1);
    cudaGetSymbolAddress((void**)&gh2, g_gh2);
    cudaGetSymbolAddress((void**)&om,  g_om);
    cudaGetSymbolAddress((void**)&e1,  g_e1);
    cudaGetSymbolAddress((void**)&e2,  g_e2);
    cudaGetSymbolAddress((void**)&e3,  g_e3);
    cudaGetSymbolAddress((void**)&hd,  g_hd);
    cudaGetSymbolAddress((void**)&hbias, g_hbias);
    unsigned char *bi1,*bi2,*bi3,*bg1,*bg2,*be1,*be2,*be3,*bhd;
    cudaGetSymbolAddress((void**)&bi1, s_bi1);
    cudaGetSymbolAddress((void**)&bi2, s_bi2);
    cudaGetSymbolAddress((void**)&bi3, s_bi3);
    cudaGetSymbolAddress((void**)&bg1, s_bg1);
    cudaGetSymbolAddress((void**)&bg2, s_bg2);
    cudaGetSymbolAddress((void**)&be1, s_be1);
    cudaGetSymbolAddress((void**)&be2, s_be2);
    cudaGetSymbolAddress((void**)&be3, s_be3);
    cudaGetSymbolAddress((void**)&bhd, s_bhd);

    // weight packing (chunk-exact block images)
    prep_blocks<<<NB_I1, 256>>>(iw1, bi1, 1027, 256, KP_I1, 1);
    prep_blocks<<<NB_I2, 256>>>(iw2, bi2, 256, 256, 256, 1);
    prep_blocks<<<NB_I3, 256>>>(iw3, bi3, 256, 256, 256, 1);
    prep_blocks<<<NB_G1, 256>>>(gw1, bg1, 1830, 512, KP_G1, 1);
    prep_blocks<<<NB_G2, 256>>>(gw2, bg2, 512, 256, 512, 1);
    prep_blocks<<<NB_E1, 256>>>(ew1, be1, 2086, 512, KP_E1, NE);
    prep_blocks<<<NB_E2, 256>>>(ew2, be2, 512, 512, 512, NE);
    prep_blocks<<<NB_E3, 256>>>(ew3, be3, 512, 512, 512, NE);
    prep_blocks_hd<<<NB_HD, 256>>>(pw, tw, dw, vw, bhd);
    prep_hbias<<<8, 256>>>(pb, tb, db, vb, hbias);

    assemble_frame<<<(BSZ * DF + 255) / 256, 256>>>(rot, tr, verts, dists);

    const int GY = BSZ / 128;  // 32
    gemm_mma<<<dim3(2, GY), 256, SMEM_BYTES>>>(bps, 1024, ogt, 1024, bi1, nullptr, ib1,
                                               ih1, 256, 256, 1027, KP_I1, 1, 0, 1);
    gemm_mma<<<dim3(2, GY), 256, SMEM_BYTES>>>(ih1, 256, nullptr, 0, bi2, nullptr, ib2,
                                               ih2, 256, 256, 256, 256, 1, 0, 1);
    gemm_mma<<<dim3(2, GY), 256, SMEM_BYTES>>>(ih2, 256, nullptr, 0, bi3, nullptr, ib3,
                                               h0 + 1830, DPD, 256, 256, 256, 1, 0, 1);
    gemm_mma<<<dim3(4, GY), 256, SMEM_BYTES>>>(h0, DPD, nullptr, 0, bg1, nullptr, gb1,
                                               gh1, 512, 512, 1830, KP_G1, 1, 0, 1);
    gemm_mma<<<dim3(2, GY), 256, SMEM_BYTES>>>(gh1, 512, nullptr, 0, bg2, nullptr, gb2,
                                               gh2, 256, 256, 512, 512, 1, 0, 1);
    gate3_softmax<<<BSZ / 8, 256>>>(gh2, gw3, gb3, om);
    gemm_mma<<<dim3(4, GY), 256, SMEM_BYTES>>>(h0, DPD, nullptr, 0, be1, om, eb1,
                                               e1, DH, DH, DPD, KP_E1, NE, 1, 1);
    gemm_mma<<<dim3(4, GY), 256, SMEM_BYTES>>>(e1, DH, nullptr, 0, be2, om, eb2,
                                               e2, DH, DH, DH, DH, NE, 1, 1);
    gemm_mma<<<dim3(4, GY), 256, SMEM_BYTES>>>(e2, DH, nullptr, 0, be3, om, eb3,
                                               e3, DH, DH, DH, DH, NE, 1, 1);
    gemm_mma<<<dim3(15, GY), 256, SMEM_BYTES>>>(e3, DH, nullptr, 0, bhd, nullptr, hbias,
                                                hd, DF, DF, DH, DH, 1, 0, 0);
    post_pose<<<(BSZ * 55 + 255) / 256, 256>>>(hd, out);
    post_copy<<<(BSZ * 1500 + 255) / 256, 256>>>(hd, out);
}